// round 14
// baseline (speedup 1.0000x reference)
#include <cuda_runtime.h>
#include <cuda_fp16.h>
#include <math.h>
#include <stdint.h>

// Problem constants
#define T_    4096
#define H_    1024
#define F_    4096
#define E_    8
#define KTOP_ 2
#define S_    (T_ * KTOP_)

// GEMM tiling: CTA 128x128x64(halves), 8 warps of 64x32, fp16 m16n8k16
#define BM     128
#define BN     128
#define BK     64
#define NTH    256
#define STAGES 3

// A rows: 64 halves padded to 144B (9 segs); B k-rows: 128 halves padded to 272B (17 segs)
#define ASTB 144
#define BSTB 272
#define ASZ  (BM * ASTB)           // 18432 B
#define BSZ  (BK * BSTB)           // 17408 B
#define STG  (ASZ + BSZ)           // 35840 B
#define SMEM_TOTAL (STAGES * STG)  // 107520 B (2 CTAs/SM)

// ---------------------------------------------------------------------------
// Scratch (device globals)
// ---------------------------------------------------------------------------
__device__ int    g_is64;
__device__ int    g_cnt[E_], g_off[E_], g_fill[E_];
__device__ int    g_tok[S_], g_orig[S_];
__device__ float  g_cw[S_];
__device__ __half g_xh[(size_t)T_ * H_];         // 8 MB   hidden fp16
__device__ __half g_w1h[(size_t)E_ * H_ * F_];   // 67 MB  W1 fp16 [e][H][F]
__device__ __half g_w2h[(size_t)E_ * F_ * H_];   // 67 MB  W2 fp16 [e][F][H]
__device__ __half g_h16[(size_t)S_ * F_];        // 64 MB  gelu activations fp16
__device__ float  g_y[(size_t)S_ * H_];          // 32 MB

__device__ __forceinline__ int sel_get(const void* sel, int i) {
    return g_is64 ? (int)((const long long*)sel)[i] : ((const int*)sel)[i];
}
__device__ __forceinline__ float gelu_exact(float x) {
    return 0.5f * x * (1.0f + erff(x * 0.70710678118654752f));
}
__device__ __forceinline__ uint32_t smem_u32(const void* p) {
    uint32_t a;
    asm("{ .reg .u64 t; cvta.to.shared.u64 t, %1; cvt.u32.u64 %0, t; }" : "=r"(a) : "l"(p));
    return a;
}
__device__ __forceinline__ void cvt_store4(uint32_t* dst, const float4* src, int j) {
    float4 v = src[j];
    __half2 h0 = __floats2half2_rn(v.x, v.y);
    __half2 h1 = __floats2half2_rn(v.z, v.w);
    dst[2 * j]     = *(uint32_t*)&h0;
    dst[2 * j + 1] = *(uint32_t*)&h1;
}

// cp.async 16B with runtime src-size (0 => zero-fill)
__device__ __forceinline__ void cp16(uint32_t dst, const void* src, uint32_t nbytes) {
    asm volatile("cp.async.cg.shared.global [%0], [%1], 16, %2;"
                 :: "r"(dst), "l"(src), "r"(nbytes) : "memory");
}
#define CP_COMMIT() asm volatile("cp.async.commit_group;" ::: "memory")
#define CP_WAIT(n)  asm volatile("cp.async.wait_group %0;" :: "n"(n) : "memory")

#define LDMX4(r0, r1, r2, r3, addr)                                              \
    asm volatile("ldmatrix.sync.aligned.m8n8.x4.shared.b16 {%0,%1,%2,%3}, [%4];" \
        : "=r"(r0), "=r"(r1), "=r"(r2), "=r"(r3) : "r"(addr))

#define LDMX4T(r0, r1, r2, r3, addr)                                             \
    asm volatile("ldmatrix.sync.aligned.m8n8.x4.trans.shared.b16 {%0,%1,%2,%3}, [%4];" \
        : "=r"(r0), "=r"(r1), "=r"(r2), "=r"(r3) : "r"(addr))

// ---------------------------------------------------------------------------
// Prep: block 0 does routing (detect + histogram + prefix + scatter);
// remaining blocks convert hidden + W1 to fp16 (grid-stride, branch-free).
// ---------------------------------------------------------------------------
#define N4_X  (T_ * H_ / 4)
#define N4_W  (E_ * H_ * F_ / 4)

__global__ void k_prep(const void* sel, const float* __restrict__ ew,
                       const float4* __restrict__ x, const float4* __restrict__ w1) {
    if (blockIdx.x == 0) {
        __shared__ int h[E_];
        __shared__ int bad;
        int t = threadIdx.x;
        if (t == 0) bad = 0;
        if (t < E_) h[t] = 0;
        __syncthreads();
        const long long* s64 = (const long long*)sel;
        for (int i = t; i < S_ / 2; i += blockDim.x) {
            long long v = s64[i];
            if (v < 0 || v >= E_) bad = 1;
        }
        __syncthreads();
        if (t == 0) g_is64 = bad ? 0 : 1;
        __syncthreads();
        for (int i = t; i < S_; i += blockDim.x) {
            int e = sel_get(sel, i);
            if (e >= 0 && e < E_) atomicAdd(&h[e], 1);
        }
        __syncthreads();
        if (t == 0) {
            int a = 0;
            for (int e = 0; e < E_; e++) { g_off[e] = a; a += h[e]; g_cnt[e] = h[e]; g_fill[e] = 0; }
        }
        __syncthreads();
        for (int i = t; i < S_; i += blockDim.x) {
            int e = sel_get(sel, i);
            if (e >= 0 && e < E_) {
                int p = g_off[e] + atomicAdd(&g_fill[e], 1);
                g_tok[p] = i / KTOP_; g_orig[p] = i; g_cw[p] = ew[i];
            }
        }
    } else {
        const int gid    = (blockIdx.x - 1) * blockDim.x + threadIdx.x;
        const int stride = (gridDim.x - 1) * blockDim.x;
        for (int i = gid; i < N4_X; i += stride) cvt_store4((uint32_t*)g_xh, x, i);
        for (int i = gid; i < N4_W; i += stride) cvt_store4((uint32_t*)g_w1h, w1, i);
    }
}

// ---------------------------------------------------------------------------
// Grouped GEMM (R13 golden config): mma.sync m16n8k16 fp16, ldmatrix(+trans),
// pipelined stage barrier at ks==3 (16 MMAs queued across the barrier).
// MODE 0: g_h16 = fp16(gelu(gather(g_xh) @ W1 + b1)); ALSO converts its grid
//         slice of W2 fp32 -> g_w2h after the main body (hidden under compute).
// MODE 1: g_y[orig] = cw * (g_h16 @ W2 + b2)
// ---------------------------------------------------------------------------
#define MMA_F16(c, a0, a1, a2, a3, b0, b1)                                       \
    asm volatile("mma.sync.aligned.m16n8k16.row.col.f32.f16.f16.f32 "            \
        "{%0,%1,%2,%3}, {%4,%5,%6,%7}, {%8,%9}, {%0,%1,%2,%3};"                  \
        : "+f"((c)[0]), "+f"((c)[1]), "+f"((c)[2]), "+f"((c)[3])                  \
        : "r"(a0), "r"(a1), "r"(a2), "r"(a3), "r"(b0), "r"(b1))

template<int KDIM, int NDIM, int MODE>
__global__ void __launch_bounds__(NTH, 2)
k_mma(const __half* __restrict__ X, const __half* __restrict__ W,
      const float* __restrict__ bias, const float4* __restrict__ w2src)
{
    int mt = blockIdx.y;
    int e = -1, m0 = 0, ne = 0, acc = 0;
    #pragma unroll
    for (int i = 0; i < E_; i++) {
        int n = g_cnt[i]; int nt = (n + BM - 1) / BM;
        if (e < 0 && mt < acc + nt) { e = i; m0 = (mt - acc) * BM; ne = n; }
        acc += nt;
    }

    if (e >= 0) {
        const int n0  = blockIdx.x * BN;
        const int tid = threadIdx.x;
        const int off = g_off[e];

        extern __shared__ char smem[];
        const uint32_t sbase = smem_u32(smem);

        // ---- A staging: rows (tid>>3)+32i, seg tid&7 ----
        const int a_seg = tid & 7;
        const int a_row0 = tid >> 3;
        const __half* aptr[4]; uint32_t abytes[4];
        #pragma unroll
        for (int i = 0; i < 4; i++) {
            int row = a_row0 + 32 * i;
            int m = m0 + row;
            bool v = (m < ne);
            int gi = off + (v ? m : 0);
            const __half* src = (MODE == 0) ? X + (size_t)g_tok[gi] * KDIM
                                            : g_h16 + (size_t)gi * KDIM;
            aptr[i]   = src + a_seg * 8;
            abytes[i] = v ? 16u : 0u;
        }
        const uint32_t a_s0 = (uint32_t)(a_row0 * ASTB + a_seg * 16);

        // ---- B staging: k-row (tid>>4)+16i, seg tid&15 ----
        const __half* bbase = W + (size_t)e * KDIM * NDIM + n0
                            + (size_t)(tid >> 4) * NDIM + (tid & 15) * 8;
        const uint32_t b_s0 = (uint32_t)((tid >> 4) * BSTB + (tid & 15) * 16);

        constexpr int KB = KDIM / BK;

        auto issue = [&](int stage, int kb) {
            uint32_t Ab = sbase + stage * STG;
            uint32_t Bb = Ab + ASZ;
            const int k0 = kb * BK;
            #pragma unroll
            for (int i = 0; i < 4; i++)
                cp16(Ab + a_s0 + (uint32_t)(i * 32 * ASTB), aptr[i] + k0, abytes[i]);
            #pragma unroll
            for (int i = 0; i < 4; i++)
                cp16(Bb + b_s0 + (uint32_t)(i * 16 * BSTB),
                     bbase + (size_t)(k0 + i * 16) * NDIM, 16u);
        };

        // ---- fragment geometry: 8 warps = 2m x 4n, each 64x32 ----
        const int lane = tid & 31, wid = tid >> 5;
        const int warp_m = (wid >> 2) * 64;
        const int warp_n = (wid & 3) * 32;
        const int fg = lane >> 2;
        const int ft = lane & 3;

        const uint32_t a_lm = (uint32_t)((warp_m + (lane & 15)) * ASTB + (lane >> 4) * 16);
        const uint32_t b_lm = (uint32_t)((lane & 15) * BSTB + (warp_n + (lane >> 4) * 8) * 2);

        float c[4][4][4];
        #pragma unroll
        for (int mf = 0; mf < 4; mf++)
            #pragma unroll
            for (int nf = 0; nf < 4; nf++)
                #pragma unroll
                for (int r = 0; r < 4; r++) c[mf][nf][r] = 0.f;

        #pragma unroll
        for (int s = 0; s < STAGES - 1; s++) { issue(s, s); CP_COMMIT(); }
        CP_WAIT(STAGES - 2);        // chunk 0 landed
        __syncthreads();

        for (int kb = 0; kb < KB; kb++) {
            if (kb + STAGES - 1 < KB) issue((kb + STAGES - 1) % STAGES, kb + STAGES - 1);
            CP_COMMIT();

            const int buf = kb % STAGES;
            const uint32_t Abuf = sbase + buf * STG + a_lm;
            const uint32_t Bbuf = sbase + buf * STG + ASZ + b_lm;

            #pragma unroll
            for (int ks = 0; ks < 4; ks++) {
                uint32_t a[4][4];
                #pragma unroll
                for (int mf = 0; mf < 4; mf++)
                    LDMX4(a[mf][0], a[mf][1], a[mf][2], a[mf][3],
                          Abuf + (uint32_t)(mf * 16 * ASTB + ks * 32));
                uint32_t b[4][2];
                #pragma unroll
                for (int g = 0; g < 2; g++)
                    LDMX4T(b[2 * g][0], b[2 * g][1], b[2 * g + 1][0], b[2 * g + 1][1],
                           Bbuf + (uint32_t)(ks * 16 * BSTB + g * 32));

                // Pipelined barrier: all SMEM reads of this chunk are in
                // registers; 16 MMAs remain queued to hide the post-barrier
                // LDSM storm of the next chunk.
                if (ks == 3 && kb + 1 < KB) {
                    CP_WAIT(STAGES - 2);
                    __syncthreads();
                }

                #pragma unroll
                for (int mf = 0; mf < 4; mf++)
                    #pragma unroll
                    for (int nf = 0; nf < 4; nf++)
                        MMA_F16(c[mf][nf], a[mf][0], a[mf][1], a[mf][2], a[mf][3],
                                b[nf][0], b[nf][1]);
            }
        }

        // ---- epilogue ----
        const float* bb = bias + (size_t)e * NDIM + n0;
        #pragma unroll
        for (int mf = 0; mf < 4; mf++) {
            #pragma unroll
            for (int half = 0; half < 2; half++) {
                int r = warp_m + mf * 16 + fg + half * 8;
                int m = m0 + r;
                if (m >= ne) continue;
                int gi = off + m;
                if (MODE == 0) {
                    __half* drow = g_h16 + (size_t)gi * F_ + n0;
                    #pragma unroll
                    for (int nf = 0; nf < 4; nf++) {
                        int col = warp_n + nf * 8 + 2 * ft;
                        float2 bv = *(const float2*)(bb + col);
                        float v0 = gelu_exact(c[mf][nf][half * 2 + 0] + bv.x);
                        float v1 = gelu_exact(c[mf][nf][half * 2 + 1] + bv.y);
                        __half2 hv = __floats2half2_rn(v0, v1);
                        *(uint32_t*)(drow + col) = *(uint32_t*)&hv;
                    }
                } else {
                    float cw = g_cw[gi];
                    float* drow = g_y + (size_t)g_orig[gi] * H_ + n0;
                    #pragma unroll
                    for (int nf = 0; nf < 4; nf++) {
                        int col = warp_n + nf * 8 + 2 * ft;
                        float2 bv = *(const float2*)(bb + col);
                        float2 o;
                        o.x = cw * (c[mf][nf][half * 2 + 0] + bv.x);
                        o.y = cw * (c[mf][nf][half * 2 + 1] + bv.y);
                        *(float2*)(drow + col) = o;
                    }
                }
            }
        }
    }

    // ---- W2 convert (MODE 0 only): every CTA, including early-out ones,
    // converts its grid slice; hidden under other CTAs' tensor work. ----
    if (MODE == 0) {
        const int cid  = blockIdx.y * gridDim.x + blockIdx.x;
        const int nblk = gridDim.x * gridDim.y;
        for (int i = cid * NTH + threadIdx.x; i < N4_W; i += nblk * NTH)
            cvt_store4((uint32_t*)g_w2h, w2src, i);
    }
}

// ---------------------------------------------------------------------------
// Final reduce over the K=2 slots of each token
// ---------------------------------------------------------------------------
__global__ void k_reduce(const void* sel, float* __restrict__ out) {
    int i4 = blockIdx.x * blockDim.x + threadIdx.x;
    if (i4 >= T_ * H_ / 4) return;
    int t = i4 / (H_ / 4);
    int c = i4 % (H_ / 4);
    float4 s = make_float4(0.f, 0.f, 0.f, 0.f);
    #pragma unroll
    for (int k = 0; k < KTOP_; k++) {
        int e = sel_get(sel, t * KTOP_ + k);
        if (e >= 0 && e < E_) {
            float4 v = ((const float4*)g_y)[(size_t)(t * KTOP_ + k) * (H_ / 4) + c];
            s.x += v.x; s.y += v.y; s.z += v.z; s.w += v.w;
        }
    }
    ((float4*)out)[i4] = s;
}

// ---------------------------------------------------------------------------
// Launch
// ---------------------------------------------------------------------------
extern "C" void kernel_launch(void* const* d_in, const int* in_sizes, int n_in,
                              void* d_out, int out_size) {
    const float* hidden = (const float*)d_in[0];
    const float* ew     = (const float*)d_in[1];
    const float* W1     = (const float*)d_in[2];
    const float* b1     = (const float*)d_in[3];
    const float* W2     = (const float*)d_in[4];
    const float* b2     = (const float*)d_in[5];
    const void*  sel    = d_in[6];
    float* out = (float*)d_out;

    cudaFuncSetAttribute(k_mma<H_, F_, 0>, cudaFuncAttributeMaxDynamicSharedMemorySize, SMEM_TOTAL);
    cudaFuncSetAttribute(k_mma<F_, H_, 1>, cudaFuncAttributeMaxDynamicSharedMemorySize, SMEM_TOTAL);

    __half* xh;  cudaGetSymbolAddress((void**)&xh,  g_xh);
    __half* w1h; cudaGetSymbolAddress((void**)&w1h, g_w1h);
    __half* w2h; cudaGetSymbolAddress((void**)&w2h, g_w2h);

    // Block 0 routes; blocks 1..2048 convert hidden + W1.
    k_prep<<<2049, 256>>>(sel, ew, (const float4*)hidden, (const float4*)W1);

    const int MT = S_ / BM + E_;  // 72 worst-case m-tiles
    k_mma<H_, F_, 0><<<dim3(F_ / BN, MT), NTH, SMEM_TOTAL>>>(xh, w1h, b1, (const float4*)W2);
    k_mma<F_, H_, 1><<<dim3(H_ / BN, MT), NTH, SMEM_TOTAL>>>(nullptr, w2h, b2, nullptr);

    k_reduce<<<(T_ * H_ / 4 + 255) / 256, 256>>>(sel, out);
}

// round 15
// speedup vs baseline: 1.0001x; 1.0001x over previous
#include <cuda_runtime.h>
#include <cuda_fp16.h>
#include <math.h>
#include <stdint.h>

// Problem constants
#define T_    4096
#define H_    1024
#define F_    4096
#define E_    8
#define KTOP_ 2
#define S_    (T_ * KTOP_)

// GEMM tiling: CTA 128x128x64(halves), 8 warps of 64x32, fp16 m16n8k16
#define BM     128
#define BN     128
#define BK     64
#define NTH    256
#define STAGES 3

// A rows: 64 halves padded to 144B (9 segs); B k-rows: 128 halves padded to 272B (17 segs)
#define ASTB 144
#define BSTB 272
#define ASZ  (BM * ASTB)           // 18432 B
#define BSZ  (BK * BSTB)           // 17408 B
#define STG  (ASZ + BSZ)           // 35840 B
#define SMEM_TOTAL (STAGES * STG)  // 107520 B (2 CTAs/SM)

// ---------------------------------------------------------------------------
// Scratch (device globals)
// ---------------------------------------------------------------------------
__device__ int    g_is64;
__device__ int    g_cnt[E_], g_off[E_], g_fill[E_];
__device__ int    g_tok[S_], g_orig[S_];
__device__ float  g_cw[S_];
__device__ __half g_xh[(size_t)T_ * H_];         // 8 MB   hidden fp16
__device__ __half g_w1h[(size_t)E_ * H_ * F_];   // 67 MB  W1 fp16 [e][H][F]
__device__ __half g_w2h[(size_t)E_ * F_ * H_];   // 67 MB  W2 fp16 [e][F][H]
__device__ __half g_h16[(size_t)S_ * F_];        // 64 MB  gelu activations fp16
__device__ float  g_y[(size_t)S_ * H_];          // 32 MB

__device__ __forceinline__ int sel_get(const void* sel, int i) {
    return g_is64 ? (int)((const long long*)sel)[i] : ((const int*)sel)[i];
}
__device__ __forceinline__ float gelu_exact(float x) {
    return 0.5f * x * (1.0f + erff(x * 0.70710678118654752f));
}
__device__ __forceinline__ uint32_t smem_u32(const void* p) {
    uint32_t a;
    asm("{ .reg .u64 t; cvta.to.shared.u64 t, %1; cvt.u32.u64 %0, t; }" : "=r"(a) : "l"(p));
    return a;
}
__device__ __forceinline__ void cvt_store4(uint32_t* dst, const float4* src, int j) {
    float4 v = src[j];
    __half2 h0 = __floats2half2_rn(v.x, v.y);
    __half2 h1 = __floats2half2_rn(v.z, v.w);
    dst[2 * j]     = *(uint32_t*)&h0;
    dst[2 * j + 1] = *(uint32_t*)&h1;
}

// cp.async 16B with runtime src-size (0 => zero-fill)
__device__ __forceinline__ void cp16(uint32_t dst, const void* src, uint32_t nbytes) {
    asm volatile("cp.async.cg.shared.global [%0], [%1], 16, %2;"
                 :: "r"(dst), "l"(src), "r"(nbytes) : "memory");
}
#define CP_COMMIT() asm volatile("cp.async.commit_group;" ::: "memory")
#define CP_WAIT(n)  asm volatile("cp.async.wait_group %0;" :: "n"(n) : "memory")

#define LDMX4(r0, r1, r2, r3, addr)                                              \
    asm volatile("ldmatrix.sync.aligned.m8n8.x4.shared.b16 {%0,%1,%2,%3}, [%4];" \
        : "=r"(r0), "=r"(r1), "=r"(r2), "=r"(r3) : "r"(addr))

#define LDMX4T(r0, r1, r2, r3, addr)                                             \
    asm volatile("ldmatrix.sync.aligned.m8n8.x4.trans.shared.b16 {%0,%1,%2,%3}, [%4];" \
        : "=r"(r0), "=r"(r1), "=r"(r2), "=r"(r3) : "r"(addr))

// ---------------------------------------------------------------------------
// Prep: block 0 routes (detect + histogram + prefix + scatter); blocks
// 1..gridDim-1 convert hidden, W1, W2 to fp16 (grid-stride).
// ---------------------------------------------------------------------------
#define N4_X  (T_ * H_ / 4)
#define N4_W  (E_ * H_ * F_ / 4)

__global__ void k_prep(const void* sel, const float* __restrict__ ew,
                       const float4* __restrict__ x, const float4* __restrict__ w1,
                       const float4* __restrict__ w2) {
    if (blockIdx.x == 0) {
        __shared__ int h[E_];
        __shared__ int bad;
        int t = threadIdx.x;
        if (t == 0) bad = 0;
        if (t < E_) h[t] = 0;
        __syncthreads();
        const long long* s64 = (const long long*)sel;
        for (int i = t; i < S_ / 2; i += blockDim.x) {
            long long v = s64[i];
            if (v < 0 || v >= E_) bad = 1;
        }
        __syncthreads();
        if (t == 0) g_is64 = bad ? 0 : 1;
        __syncthreads();
        for (int i = t; i < S_; i += blockDim.x) {
            int e = sel_get(sel, i);
            if (e >= 0 && e < E_) atomicAdd(&h[e], 1);
        }
        __syncthreads();
        if (t == 0) {
            int a = 0;
            for (int e = 0; e < E_; e++) { g_off[e] = a; a += h[e]; g_cnt[e] = h[e]; g_fill[e] = 0; }
        }
        __syncthreads();
        for (int i = t; i < S_; i += blockDim.x) {
            int e = sel_get(sel, i);
            if (e >= 0 && e < E_) {
                int p = g_off[e] + atomicAdd(&g_fill[e], 1);
                g_tok[p] = i / KTOP_; g_orig[p] = i; g_cw[p] = ew[i];
            }
        }
    } else {
        const int gid    = (blockIdx.x - 1) * blockDim.x + threadIdx.x;
        const int stride = (gridDim.x - 1) * blockDim.x;
        for (int i = gid; i < N4_X; i += stride) cvt_store4((uint32_t*)g_xh, x, i);
        for (int i = gid; i < N4_W; i += stride) cvt_store4((uint32_t*)g_w1h, w1, i);
        for (int i = gid; i < N4_W; i += stride) cvt_store4((uint32_t*)g_w2h, w2, i);
    }
}

// ---------------------------------------------------------------------------
// Grouped GEMM (R13 golden config): mma.sync m16n8k16 fp16, ldmatrix(+trans),
// pipelined stage barrier at ks==3 (16 MMAs queued across the barrier).
// MODE 0: g_h16 = fp16(gelu(gather(g_xh) @ W1 + b1))
// MODE 1: g_y[orig] = cw * (g_h16 @ W2 + b2)
// ---------------------------------------------------------------------------
#define MMA_F16(c, a0, a1, a2, a3, b0, b1)                                       \
    asm volatile("mma.sync.aligned.m16n8k16.row.col.f32.f16.f16.f32 "            \
        "{%0,%1,%2,%3}, {%4,%5,%6,%7}, {%8,%9}, {%0,%1,%2,%3};"                  \
        : "+f"((c)[0]), "+f"((c)[1]), "+f"((c)[2]), "+f"((c)[3])                  \
        : "r"(a0), "r"(a1), "r"(a2), "r"(a3), "r"(b0), "r"(b1))

template<int KDIM, int NDIM, int MODE>
__global__ void __launch_bounds__(NTH, 2)
k_mma(const __half* __restrict__ X, const __half* __restrict__ W,
      const float* __restrict__ bias)
{
    int mt = blockIdx.y;
    int e = -1, m0 = 0, ne = 0, acc = 0;
    #pragma unroll
    for (int i = 0; i < E_; i++) {
        int n = g_cnt[i]; int nt = (n + BM - 1) / BM;
        if (e < 0 && mt < acc + nt) { e = i; m0 = (mt - acc) * BM; ne = n; }
        acc += nt;
    }
    if (e < 0) return;

    const int n0  = blockIdx.x * BN;
    const int tid = threadIdx.x;
    const int off = g_off[e];

    extern __shared__ char smem[];
    const uint32_t sbase = smem_u32(smem);

    // ---- A staging: rows (tid>>3)+32i, seg tid&7 ----
    const int a_seg = tid & 7;
    const int a_row0 = tid >> 3;
    const __half* aptr[4]; uint32_t abytes[4];
    #pragma unroll
    for (int i = 0; i < 4; i++) {
        int row = a_row0 + 32 * i;
        int m = m0 + row;
        bool v = (m < ne);
        int gi = off + (v ? m : 0);
        const __half* src = (MODE == 0) ? X + (size_t)g_tok[gi] * KDIM
                                        : g_h16 + (size_t)gi * KDIM;
        aptr[i]   = src + a_seg * 8;
        abytes[i] = v ? 16u : 0u;
    }
    const uint32_t a_s0 = (uint32_t)(a_row0 * ASTB + a_seg * 16);

    // ---- B staging: k-row (tid>>4)+16i, seg tid&15 ----
    const __half* bbase = W + (size_t)e * KDIM * NDIM + n0
                        + (size_t)(tid >> 4) * NDIM + (tid & 15) * 8;
    const uint32_t b_s0 = (uint32_t)((tid >> 4) * BSTB + (tid & 15) * 16);

    constexpr int KB = KDIM / BK;

    auto issue = [&](int stage, int kb) {
        uint32_t Ab = sbase + stage * STG;
        uint32_t Bb = Ab + ASZ;
        const int k0 = kb * BK;
        #pragma unroll
        for (int i = 0; i < 4; i++)
            cp16(Ab + a_s0 + (uint32_t)(i * 32 * ASTB), aptr[i] + k0, abytes[i]);
        #pragma unroll
        for (int i = 0; i < 4; i++)
            cp16(Bb + b_s0 + (uint32_t)(i * 16 * BSTB),
                 bbase + (size_t)(k0 + i * 16) * NDIM, 16u);
    };

    // ---- fragment geometry: 8 warps = 2m x 4n, each 64x32 ----
    const int lane = tid & 31, wid = tid >> 5;
    const int warp_m = (wid >> 2) * 64;
    const int warp_n = (wid & 3) * 32;
    const int fg = lane >> 2;
    const int ft = lane & 3;

    const uint32_t a_lm = (uint32_t)((warp_m + (lane & 15)) * ASTB + (lane >> 4) * 16);
    const uint32_t b_lm = (uint32_t)((lane & 15) * BSTB + (warp_n + (lane >> 4) * 8) * 2);

    float c[4][4][4];
    #pragma unroll
    for (int mf = 0; mf < 4; mf++)
        #pragma unroll
        for (int nf = 0; nf < 4; nf++)
            #pragma unroll
            for (int r = 0; r < 4; r++) c[mf][nf][r] = 0.f;

    #pragma unroll
    for (int s = 0; s < STAGES - 1; s++) { issue(s, s); CP_COMMIT(); }
    CP_WAIT(STAGES - 2);        // chunk 0 landed
    __syncthreads();

    for (int kb = 0; kb < KB; kb++) {
        if (kb + STAGES - 1 < KB) issue((kb + STAGES - 1) % STAGES, kb + STAGES - 1);
        CP_COMMIT();

        const int buf = kb % STAGES;
        const uint32_t Abuf = sbase + buf * STG + a_lm;
        const uint32_t Bbuf = sbase + buf * STG + ASZ + b_lm;

        #pragma unroll
        for (int ks = 0; ks < 4; ks++) {
            uint32_t a[4][4];
            #pragma unroll
            for (int mf = 0; mf < 4; mf++)
                LDMX4(a[mf][0], a[mf][1], a[mf][2], a[mf][3],
                      Abuf + (uint32_t)(mf * 16 * ASTB + ks * 32));
            uint32_t b[4][2];
            #pragma unroll
            for (int g = 0; g < 2; g++)
                LDMX4T(b[2 * g][0], b[2 * g][1], b[2 * g + 1][0], b[2 * g + 1][1],
                       Bbuf + (uint32_t)(ks * 16 * BSTB + g * 32));

            // Pipelined barrier: all SMEM reads of this chunk are in registers;
            // 16 MMAs remain queued to hide the post-barrier LDSM storm.
            if (ks == 3 && kb + 1 < KB) {
                CP_WAIT(STAGES - 2);
                __syncthreads();
            }

            #pragma unroll
            for (int mf = 0; mf < 4; mf++)
                #pragma unroll
                for (int nf = 0; nf < 4; nf++)
                    MMA_F16(c[mf][nf], a[mf][0], a[mf][1], a[mf][2], a[mf][3],
                            b[nf][0], b[nf][1]);
        }
    }

    // ---- epilogue ----
    const float* bb = bias + (size_t)e * NDIM + n0;
    #pragma unroll
    for (int mf = 0; mf < 4; mf++) {
        #pragma unroll
        for (int half = 0; half < 2; half++) {
            int r = warp_m + mf * 16 + fg + half * 8;
            int m = m0 + r;
            if (m >= ne) continue;
            int gi = off + m;
            if (MODE == 0) {
                __half* drow = g_h16 + (size_t)gi * F_ + n0;
                #pragma unroll
                for (int nf = 0; nf < 4; nf++) {
                    int col = warp_n + nf * 8 + 2 * ft;
                    float2 bv = *(const float2*)(bb + col);
                    float v0 = gelu_exact(c[mf][nf][half * 2 + 0] + bv.x);
                    float v1 = gelu_exact(c[mf][nf][half * 2 + 1] + bv.y);
                    __half2 hv = __floats2half2_rn(v0, v1);
                    *(uint32_t*)(drow + col) = *(uint32_t*)&hv;
                }
            } else {
                float cw = g_cw[gi];
                float* drow = g_y + (size_t)g_orig[gi] * H_ + n0;
                #pragma unroll
                for (int nf = 0; nf < 4; nf++) {
                    int col = warp_n + nf * 8 + 2 * ft;
                    float2 bv = *(const float2*)(bb + col);
                    float2 o;
                    o.x = cw * (c[mf][nf][half * 2 + 0] + bv.x);
                    o.y = cw * (c[mf][nf][half * 2 + 1] + bv.y);
                    *(float2*)(drow + col) = o;
                }
            }
        }
    }
}

// ---------------------------------------------------------------------------
// Final reduce over the K=2 slots of each token
// ---------------------------------------------------------------------------
__global__ void k_reduce(const void* sel, float* __restrict__ out) {
    int i4 = blockIdx.x * blockDim.x + threadIdx.x;
    if (i4 >= T_ * H_ / 4) return;
    int t = i4 / (H_ / 4);
    int c = i4 % (H_ / 4);
    float4 s = make_float4(0.f, 0.f, 0.f, 0.f);
    #pragma unroll
    for (int k = 0; k < KTOP_; k++) {
        int e = sel_get(sel, t * KTOP_ + k);
        if (e >= 0 && e < E_) {
            float4 v = ((const float4*)g_y)[(size_t)(t * KTOP_ + k) * (H_ / 4) + c];
            s.x += v.x; s.y += v.y; s.z += v.z; s.w += v.w;
        }
    }
    ((float4*)out)[i4] = s;
}

// ---------------------------------------------------------------------------
// Launch
// ---------------------------------------------------------------------------
extern "C" void kernel_launch(void* const* d_in, const int* in_sizes, int n_in,
                              void* d_out, int out_size) {
    const float* hidden = (const float*)d_in[0];
    const float* ew     = (const float*)d_in[1];
    const float* W1     = (const float*)d_in[2];
    const float* b1     = (const float*)d_in[3];
    const float* W2     = (const float*)d_in[4];
    const float* b2     = (const float*)d_in[5];
    const void*  sel    = d_in[6];
    float* out = (float*)d_out;

    cudaFuncSetAttribute(k_mma<H_, F_, 0>, cudaFuncAttributeMaxDynamicSharedMemorySize, SMEM_TOTAL);
    cudaFuncSetAttribute(k_mma<F_, H_, 1>, cudaFuncAttributeMaxDynamicSharedMemorySize, SMEM_TOTAL);

    __half* xh;  cudaGetSymbolAddress((void**)&xh,  g_xh);
    __half* w1h; cudaGetSymbolAddress((void**)&w1h, g_w1h);
    __half* w2h; cudaGetSymbolAddress((void**)&w2h, g_w2h);

    // Block 0 routes; blocks 1..4096 convert hidden + W1 + W2.
    k_prep<<<4097, 256>>>(sel, ew, (const float4*)hidden,
                          (const float4*)W1, (const float4*)W2);

    const int MT = S_ / BM + E_;  // 72 worst-case m-tiles
    k_mma<H_, F_, 0><<<dim3(F_ / BN, MT), NTH, SMEM_TOTAL>>>(xh, w1h, b1);
    k_mma<F_, H_, 1><<<dim3(H_ / BN, MT), NTH, SMEM_TOTAL>>>(nullptr, w2h, b2);

    k_reduce<<<(T_ * H_ / 4 + 255) / 256, 256>>>(sel, out);
}

// round 16
// speedup vs baseline: 1.0246x; 1.0244x over previous
#include <cuda_runtime.h>
#include <cuda_fp16.h>
#include <math.h>
#include <stdint.h>

// Problem constants
#define T_    4096
#define H_    1024
#define F_    4096
#define E_    8
#define KTOP_ 2
#define S_    (T_ * KTOP_)

// GEMM tiling: CTA 128x128x64(halves), 8 warps of 64x32, fp16 m16n8k16
#define BM     128
#define BN     128
#define BK     64
#define NTH    256
#define STAGES 3

// A rows: 64 halves padded to 144B (9 segs); B k-rows: 128 halves padded to 272B (17 segs)
#define ASTB 144
#define BSTB 272
#define ASZ  (BM * ASTB)           // 18432 B
#define BSZ  (BK * BSTB)           // 17408 B
#define STG  (ASZ + BSZ)           // 35840 B
#define SMEM_TOTAL (STAGES * STG)  // 107520 B (2 CTAs/SM)

// ---------------------------------------------------------------------------
// Scratch (device globals)
// ---------------------------------------------------------------------------
__device__ int    g_is64;
__device__ int    g_cnt[E_], g_off[E_], g_fill[E_];
__device__ int    g_tok[S_], g_orig[S_];
__device__ float  g_cw[S_];
__device__ __half g_xh[(size_t)T_ * H_];         // 8 MB   hidden fp16
__device__ __half g_w1h[(size_t)E_ * H_ * F_];   // 67 MB  W1 fp16 [e][H][F]
__device__ __half g_w2h[(size_t)E_ * F_ * H_];   // 67 MB  W2 fp16 [e][F][H]
__device__ __half g_h16[(size_t)S_ * F_];        // 64 MB  gelu activations fp16
__device__ float  g_y[(size_t)S_ * H_];          // 32 MB

__device__ __forceinline__ int sel_get(const void* sel, int i) {
    return g_is64 ? (int)((const long long*)sel)[i] : ((const int*)sel)[i];
}
__device__ __forceinline__ float gelu_exact(float x) {
    return 0.5f * x * (1.0f + erff(x * 0.70710678118654752f));
}
__device__ __forceinline__ uint32_t smem_u32(const void* p) {
    uint32_t a;
    asm("{ .reg .u64 t; cvta.to.shared.u64 t, %1; cvt.u32.u64 %0, t; }" : "=r"(a) : "l"(p));
    return a;
}
__device__ __forceinline__ void cvt_store4(uint32_t* dst, const float4* src, int j) {
    float4 v = src[j];
    __half2 h0 = __floats2half2_rn(v.x, v.y);
    __half2 h1 = __floats2half2_rn(v.z, v.w);
    dst[2 * j]     = *(uint32_t*)&h0;
    dst[2 * j + 1] = *(uint32_t*)&h1;
}

// cp.async 16B with runtime src-size (0 => zero-fill)
__device__ __forceinline__ void cp16(uint32_t dst, const void* src, uint32_t nbytes) {
    asm volatile("cp.async.cg.shared.global [%0], [%1], 16, %2;"
                 :: "r"(dst), "l"(src), "r"(nbytes) : "memory");
}
#define CP_COMMIT() asm volatile("cp.async.commit_group;" ::: "memory")
#define CP_WAIT(n)  asm volatile("cp.async.wait_group %0;" :: "n"(n) : "memory")

#define LDMX4(r0, r1, r2, r3, addr)                                              \
    asm volatile("ldmatrix.sync.aligned.m8n8.x4.shared.b16 {%0,%1,%2,%3}, [%4];" \
        : "=r"(r0), "=r"(r1), "=r"(r2), "=r"(r3) : "r"(addr))

#define LDMX4T(r0, r1, r2, r3, addr)                                             \
    asm volatile("ldmatrix.sync.aligned.m8n8.x4.trans.shared.b16 {%0,%1,%2,%3}, [%4];" \
        : "=r"(r0), "=r"(r1), "=r"(r2), "=r"(r3) : "r"(addr))

// ---------------------------------------------------------------------------
// Routing: detect + histogram + prefix + scatter, one single-block kernel.
// ---------------------------------------------------------------------------
__global__ void k_route(const void* sel, const float* __restrict__ ew) {
    __shared__ int h[E_];
    __shared__ int bad;
    int t = threadIdx.x;
    if (t == 0) bad = 0;
    if (t < E_) h[t] = 0;
    __syncthreads();
    const long long* s64 = (const long long*)sel;
    for (int i = t; i < S_ / 2; i += blockDim.x) {
        long long v = s64[i];
        if (v < 0 || v >= E_) bad = 1;
    }
    __syncthreads();
    if (t == 0) g_is64 = bad ? 0 : 1;
    __syncthreads();
    for (int i = t; i < S_; i += blockDim.x) {
        int e = sel_get(sel, i);
        if (e >= 0 && e < E_) atomicAdd(&h[e], 1);
    }
    __syncthreads();
    if (t == 0) {
        int a = 0;
        for (int e = 0; e < E_; e++) { g_off[e] = a; a += h[e]; g_cnt[e] = h[e]; g_fill[e] = 0; }
    }
    __syncthreads();
    for (int i = t; i < S_; i += blockDim.x) {
        int e = sel_get(sel, i);
        if (e >= 0 && e < E_) {
            int p = g_off[e] + atomicAdd(&g_fill[e], 1);
            g_tok[p] = i / KTOP_; g_orig[p] = i; g_cw[p] = ew[i];
        }
    }
}

// ---------------------------------------------------------------------------
// Fused fp32 -> fp16 convert over three regions (hidden, W1, W2)
// ---------------------------------------------------------------------------
#define N4_X  (T_ * H_ / 4)
#define N4_W  (E_ * H_ * F_ / 4)
__global__ void k_half3(const float4* __restrict__ x, const float4* __restrict__ w1,
                        const float4* __restrict__ w2) {
    const int total = N4_X + 2 * N4_W;
    for (int i = blockIdx.x * blockDim.x + threadIdx.x; i < total;
         i += gridDim.x * blockDim.x) {
        const float4* src; uint32_t* dst; int j;
        if (i < N4_X)             { src = x;  dst = (uint32_t*)g_xh;  j = i; }
        else if (i < N4_X + N4_W) { src = w1; dst = (uint32_t*)g_w1h; j = i - N4_X; }
        else                      { src = w2; dst = (uint32_t*)g_w2h; j = i - N4_X - N4_W; }
        cvt_store4(dst, src, j);
    }
}

// ---------------------------------------------------------------------------
// Grouped GEMM: mma.sync m16n8k16 fp16, ldmatrix(+trans).
// R13 golden config + LSU de-bursting: the cp.async refill is spread across
// the ks slots (ks0: A-refill, ks1: B-refill, ks2: commit, ks3: pipelined
// wait+barrier). One commit per kb; wait_group(1) semantics unchanged.
// MODE 0: g_h16 = fp16(gelu(gather(g_xh) @ W1 + b1))
// MODE 1: g_y[orig] = cw * (g_h16 @ W2 + b2)
// ---------------------------------------------------------------------------
#define MMA_F16(c, a0, a1, a2, a3, b0, b1)                                       \
    asm volatile("mma.sync.aligned.m16n8k16.row.col.f32.f16.f16.f32 "            \
        "{%0,%1,%2,%3}, {%4,%5,%6,%7}, {%8,%9}, {%0,%1,%2,%3};"                  \
        : "+f"((c)[0]), "+f"((c)[1]), "+f"((c)[2]), "+f"((c)[3])                  \
        : "r"(a0), "r"(a1), "r"(a2), "r"(a3), "r"(b0), "r"(b1))

template<int KDIM, int NDIM, int MODE>
__global__ void __launch_bounds__(NTH, 2)
k_mma(const __half* __restrict__ X, const __half* __restrict__ W,
      const float* __restrict__ bias)
{
    int mt = blockIdx.y;
    int e = -1, m0 = 0, ne = 0, acc = 0;
    #pragma unroll
    for (int i = 0; i < E_; i++) {
        int n = g_cnt[i]; int nt = (n + BM - 1) / BM;
        if (e < 0 && mt < acc + nt) { e = i; m0 = (mt - acc) * BM; ne = n; }
        acc += nt;
    }
    if (e < 0) return;

    const int n0  = blockIdx.x * BN;
    const int tid = threadIdx.x;
    const int off = g_off[e];

    extern __shared__ char smem[];
    const uint32_t sbase = smem_u32(smem);

    // ---- A staging: rows (tid>>3)+32i, seg tid&7 ----
    const int a_seg = tid & 7;
    const int a_row0 = tid >> 3;
    const __half* aptr[4]; uint32_t abytes[4];
    #pragma unroll
    for (int i = 0; i < 4; i++) {
        int row = a_row0 + 32 * i;
        int m = m0 + row;
        bool v = (m < ne);
        int gi = off + (v ? m : 0);
        const __half* src = (MODE == 0) ? X + (size_t)g_tok[gi] * KDIM
                                        : g_h16 + (size_t)gi * KDIM;
        aptr[i]   = src + a_seg * 8;
        abytes[i] = v ? 16u : 0u;
    }
    const uint32_t a_s0 = (uint32_t)(a_row0 * ASTB + a_seg * 16);

    // ---- B staging: k-row (tid>>4)+16i, seg tid&15 ----
    const __half* bbase = W + (size_t)e * KDIM * NDIM + n0
                        + (size_t)(tid >> 4) * NDIM + (tid & 15) * 8;
    const uint32_t b_s0 = (uint32_t)((tid >> 4) * BSTB + (tid & 15) * 16);

    constexpr int KB = KDIM / BK;

    auto issue_a = [&](int stage, int kb) {
        uint32_t Ab = sbase + stage * STG;
        const int k0 = kb * BK;
        #pragma unroll
        for (int i = 0; i < 4; i++)
            cp16(Ab + a_s0 + (uint32_t)(i * 32 * ASTB), aptr[i] + k0, abytes[i]);
    };
    auto issue_b = [&](int stage, int kb) {
        uint32_t Bb = sbase + stage * STG + ASZ;
        const int k0 = kb * BK;
        #pragma unroll
        for (int i = 0; i < 4; i++)
            cp16(Bb + b_s0 + (uint32_t)(i * 16 * BSTB),
                 bbase + (size_t)(k0 + i * 16) * NDIM, 16u);
    };

    // ---- fragment geometry: 8 warps = 2m x 4n, each 64x32 ----
    const int lane = tid & 31, wid = tid >> 5;
    const int warp_m = (wid >> 2) * 64;
    const int warp_n = (wid & 3) * 32;
    const int fg = lane >> 2;
    const int ft = lane & 3;

    const uint32_t a_lm = (uint32_t)((warp_m + (lane & 15)) * ASTB + (lane >> 4) * 16);
    const uint32_t b_lm = (uint32_t)((lane & 15) * BSTB + (warp_n + (lane >> 4) * 8) * 2);

    float c[4][4][4];
    #pragma unroll
    for (int mf = 0; mf < 4; mf++)
        #pragma unroll
        for (int nf = 0; nf < 4; nf++)
            #pragma unroll
            for (int r = 0; r < 4; r++) c[mf][nf][r] = 0.f;

    #pragma unroll
    for (int s = 0; s < STAGES - 1; s++) { issue_a(s, s); issue_b(s, s); CP_COMMIT(); }
    CP_WAIT(STAGES - 2);        // chunk 0 landed
    __syncthreads();

    for (int kb = 0; kb < KB; kb++) {
        const int buf = kb % STAGES;
        const uint32_t Abuf = sbase + buf * STG + a_lm;
        const uint32_t Bbuf = sbase + buf * STG + ASZ + b_lm;
        const int nstage = (kb + STAGES - 1) % STAGES;
        const bool do_issue = (kb + STAGES - 1 < KB);

        #pragma unroll
        for (int ks = 0; ks < 4; ks++) {
            uint32_t a[4][4];
            #pragma unroll
            for (int mf = 0; mf < 4; mf++)
                LDMX4(a[mf][0], a[mf][1], a[mf][2], a[mf][3],
                      Abuf + (uint32_t)(mf * 16 * ASTB + ks * 32));
            uint32_t b[4][2];
            #pragma unroll
            for (int g = 0; g < 2; g++)
                LDMX4T(b[2 * g][0], b[2 * g][1], b[2 * g + 1][0], b[2 * g + 1][1],
                       Bbuf + (uint32_t)(ks * 16 * BSTB + g * 32));

            // Spread refill work across ks slots (LSU de-bursting).
            if (ks == 0 && do_issue) issue_a(nstage, kb + STAGES - 1);
            if (ks == 1 && do_issue) issue_b(nstage, kb + STAGES - 1);
            if (ks == 2) CP_COMMIT();
            // Pipelined barrier: all SMEM reads of this chunk are in registers;
            // 16 MMAs remain queued to hide the post-barrier LDSM storm.
            if (ks == 3 && kb + 1 < KB) {
                CP_WAIT(STAGES - 2);
                __syncthreads();
            }

            #pragma unroll
            for (int mf = 0; mf < 4; mf++)
                #pragma unroll
                for (int nf = 0; nf < 4; nf++)
                    MMA_F16(c[mf][nf], a[mf][0], a[mf][1], a[mf][2], a[mf][3],
                            b[nf][0], b[nf][1]);
        }
    }

    // ---- epilogue ----
    const float* bb = bias + (size_t)e * NDIM + n0;
    #pragma unroll
    for (int mf = 0; mf < 4; mf++) {
        #pragma unroll
        for (int half = 0; half < 2; half++) {
            int r = warp_m + mf * 16 + fg + half * 8;
            int m = m0 + r;
            if (m >= ne) continue;
            int gi = off + m;
            if (MODE == 0) {
                __half* drow = g_h16 + (size_t)gi * F_ + n0;
                #pragma unroll
                for (int nf = 0; nf < 4; nf++) {
                    int col = warp_n + nf * 8 + 2 * ft;
                    float2 bv = *(const float2*)(bb + col);
                    float v0 = gelu_exact(c[mf][nf][half * 2 + 0] + bv.x);
                    float v1 = gelu_exact(c[mf][nf][half * 2 + 1] + bv.y);
                    __half2 hv = __floats2half2_rn(v0, v1);
                    *(uint32_t*)(drow + col) = *(uint32_t*)&hv;
                }
            } else {
                float cw = g_cw[gi];
                float* drow = g_y + (size_t)g_orig[gi] * H_ + n0;
                #pragma unroll
                for (int nf = 0; nf < 4; nf++) {
                    int col = warp_n + nf * 8 + 2 * ft;
                    float2 bv = *(const float2*)(bb + col);
                    float2 o;
                    o.x = cw * (c[mf][nf][half * 2 + 0] + bv.x);
                    o.y = cw * (c[mf][nf][half * 2 + 1] + bv.y);
                    *(float2*)(drow + col) = o;
                }
            }
        }
    }
}

// ---------------------------------------------------------------------------
// Final reduce over the K=2 slots of each token
// ---------------------------------------------------------------------------
__global__ void k_reduce(const void* sel, float* __restrict__ out) {
    int i4 = blockIdx.x * blockDim.x + threadIdx.x;
    if (i4 >= T_ * H_ / 4) return;
    int t = i4 / (H_ / 4);
    int c = i4 % (H_ / 4);
    float4 s = make_float4(0.f, 0.f, 0.f, 0.f);
    #pragma unroll
    for (int k = 0; k < KTOP_; k++) {
        int e = sel_get(sel, t * KTOP_ + k);
        if (e >= 0 && e < E_) {
            float4 v = ((const float4*)g_y)[(size_t)(t * KTOP_ + k) * (H_ / 4) + c];
            s.x += v.x; s.y += v.y; s.z += v.z; s.w += v.w;
        }
    }
    ((float4*)out)[i4] = s;
}

// ---------------------------------------------------------------------------
// Launch (R13 structure)
// ---------------------------------------------------------------------------
extern "C" void kernel_launch(void* const* d_in, const int* in_sizes, int n_in,
                              void* d_out, int out_size) {
    const float* hidden = (const float*)d_in[0];
    const float* ew     = (const float*)d_in[1];
    const float* W1     = (const float*)d_in[2];
    const float* b1     = (const float*)d_in[3];
    const float* W2     = (const float*)d_in[4];
    const float* b2     = (const float*)d_in[5];
    const void*  sel    = d_in[6];
    float* out = (float*)d_out;

    cudaFuncSetAttribute(k_mma<H_, F_, 0>, cudaFuncAttributeMaxDynamicSharedMemorySize, SMEM_TOTAL);
    cudaFuncSetAttribute(k_mma<F_, H_, 1>, cudaFuncAttributeMaxDynamicSharedMemorySize, SMEM_TOTAL);

    __half* xh;  cudaGetSymbolAddress((void**)&xh,  g_xh);
    __half* w1h; cudaGetSymbolAddress((void**)&w1h, g_w1h);
    __half* w2h; cudaGetSymbolAddress((void**)&w2h, g_w2h);

    k_route<<<1, 1024>>>(sel, ew);
    k_half3<<<4096, 256>>>((const float4*)hidden, (const float4*)W1, (const float4*)W2);

    const int MT = S_ / BM + E_;  // 72 worst-case m-tiles
    k_mma<H_, F_, 0><<<dim3(F_ / BN, MT), NTH, SMEM_TOTAL>>>(xh, w1h, b1);
    k_mma<F_, H_, 1><<<dim3(H_ / BN, MT), NTH, SMEM_TOTAL>>>(nullptr, w2h, b2);

    k_reduce<<<(T_ * H_ / 4 + 255) / 256, 256>>>(sel, out);
}

// round 17
// speedup vs baseline: 1.0357x; 1.0109x over previous
#include <cuda_runtime.h>
#include <cuda_fp16.h>
#include <math.h>
#include <stdint.h>

// Problem constants
#define T_    4096
#define H_    1024
#define F_    4096
#define E_    8
#define KTOP_ 2
#define S_    (T_ * KTOP_)

// GEMM tiling: CTA 128x128x64(halves), 8 warps of 64x32, fp16 m16n8k16
#define BM     128
#define BN     128
#define BK     64
#define NTH    256
#define STAGES 3

#define MT_    (S_ / BM + E_)      // 72 worst-case m-tiles
#define N1_    (MT_ * (F_ / BN))   // 2304 GEMM1 tiles
#define N2_    (MT_ * (H_ / BN))   // 576  GEMM2 tiles

// A rows: 64 halves padded to 144B (9 segs); B k-rows: 128 halves padded to 272B (17 segs)
#define ASTB 144
#define BSTB 272
#define ASZ  (BM * ASTB)           // 18432 B
#define BSZ  (BK * BSTB)           // 17408 B
#define STG  (ASZ + BSZ)           // 35840 B
#define SMEM_TOTAL (STAGES * STG)  // 107520 B (2 CTAs/SM)

// ---------------------------------------------------------------------------
// Scratch (device globals)
// ---------------------------------------------------------------------------
__device__ int    g_is64, g_allvalid;
__device__ int    g_cnt[E_], g_off[E_], g_fill[E_];
__device__ int    g_t1, g_t2, g_done[MT_];
__device__ int    g_tok[S_], g_orig[S_];
__device__ float  g_cw[S_];
__device__ __half g_xh[(size_t)T_ * H_];         // 8 MB   hidden fp16
__device__ __half g_w1h[(size_t)E_ * H_ * F_];   // 67 MB  W1 fp16 [e][H][F]
__device__ __half g_w2h[(size_t)E_ * F_ * H_];   // 67 MB  W2 fp16 [e][F][H]
__device__ __half g_h16[(size_t)S_ * F_];        // 64 MB  gelu activations fp16
__device__ float  g_y[(size_t)S_ * H_];          // 32 MB

__device__ __forceinline__ int sel_get(const void* sel, int i) {
    return g_is64 ? (int)((const long long*)sel)[i] : ((const int*)sel)[i];
}
__device__ __forceinline__ float gelu_exact(float x) {
    return 0.5f * x * (1.0f + erff(x * 0.70710678118654752f));
}
__device__ __forceinline__ uint32_t smem_u32(const void* p) {
    uint32_t a;
    asm("{ .reg .u64 t; cvta.to.shared.u64 t, %1; cvt.u32.u64 %0, t; }" : "=r"(a) : "l"(p));
    return a;
}
__device__ __forceinline__ void cvt_store4(uint32_t* dst, const float4* src, int j) {
    float4 v = __ldg(src + j);
    __half2 h0 = __floats2half2_rn(v.x, v.y);
    __half2 h1 = __floats2half2_rn(v.z, v.w);
    __stcs(dst + 2 * j,     *(uint32_t*)&h0);
    __stcs(dst + 2 * j + 1, *(uint32_t*)&h1);
}

// cp.async 16B with runtime src-size (0 => zero-fill); .cg = L2-direct
__device__ __forceinline__ void cp16(uint32_t dst, const void* src, uint32_t nbytes) {
    asm volatile("cp.async.cg.shared.global [%0], [%1], 16, %2;"
                 :: "r"(dst), "l"(src), "r"(nbytes) : "memory");
}
#define CP_COMMIT() asm volatile("cp.async.commit_group;" ::: "memory")
#define CP_WAIT(n)  asm volatile("cp.async.wait_group %0;" :: "n"(n) : "memory")

#define LDMX4(r0, r1, r2, r3, addr)                                              \
    asm volatile("ldmatrix.sync.aligned.m8n8.x4.shared.b16 {%0,%1,%2,%3}, [%4];" \
        : "=r"(r0), "=r"(r1), "=r"(r2), "=r"(r3) : "r"(addr))

#define LDMX4T(r0, r1, r2, r3, addr)                                             \
    asm volatile("ldmatrix.sync.aligned.m8n8.x4.trans.shared.b16 {%0,%1,%2,%3}, [%4];" \
        : "=r"(r0), "=r"(r1), "=r"(r2), "=r"(r3) : "r"(addr))

// ---------------------------------------------------------------------------
// Routing: detect + histogram + prefix + scatter; also zeroes work-queue state.
// ---------------------------------------------------------------------------
__global__ void k_route(const void* sel, const float* __restrict__ ew) {
    __shared__ int h[E_];
    __shared__ int bad;
    int t = threadIdx.x;
    if (t == 0) bad = 0;
    if (t < E_) h[t] = 0;
    if (t < MT_) g_done[t] = 0;
    if (t == 0) { g_t1 = 0; g_t2 = 0; }
    __syncthreads();
    const long long* s64 = (const long long*)sel;
    for (int i = t; i < S_ / 2; i += blockDim.x) {
        long long v = s64[i];
        if (v < 0 || v >= E_) bad = 1;
    }
    __syncthreads();
    if (t == 0) g_is64 = bad ? 0 : 1;
    __syncthreads();
    for (int i = t; i < S_; i += blockDim.x) {
        int e = sel_get(sel, i);
        if (e >= 0 && e < E_) atomicAdd(&h[e], 1);
    }
    __syncthreads();
    if (t == 0) {
        int a = 0;
        for (int e = 0; e < E_; e++) { g_off[e] = a; a += h[e]; g_cnt[e] = h[e]; g_fill[e] = 0; }
        g_allvalid = (a == S_) ? 1 : 0;
    }
    __syncthreads();
    for (int i = t; i < S_; i += blockDim.x) {
        int e = sel_get(sel, i);
        if (e >= 0 && e < E_) {
            int p = g_off[e] + atomicAdd(&g_fill[e], 1);
            g_tok[p] = i / KTOP_; g_orig[p] = i; g_cw[p] = ew[i];
        }
    }
}

// ---------------------------------------------------------------------------
// Fused fp32 -> fp16 convert over three regions (hidden, W1, W2)
// ---------------------------------------------------------------------------
#define N4_X  (T_ * H_ / 4)
#define N4_W  (E_ * H_ * F_ / 4)
__global__ void k_half3(const float4* __restrict__ x, const float4* __restrict__ w1,
                        const float4* __restrict__ w2) {
    const int total = N4_X + 2 * N4_W;
    for (int i = blockIdx.x * blockDim.x + threadIdx.x; i < total;
         i += gridDim.x * blockDim.x) {
        const float4* src; uint32_t* dst; int j;
        if (i < N4_X)             { src = x;  dst = (uint32_t*)g_xh;  j = i; }
        else if (i < N4_X + N4_W) { src = w1; dst = (uint32_t*)g_w1h; j = i - N4_X; }
        else                      { src = w2; dst = (uint32_t*)g_w2h; j = i - N4_X - N4_W; }
        cvt_store4(dst, src, j);
    }
}

// ---------------------------------------------------------------------------
// GEMM tile body (R16 golden mainloop, verbatim):
// mma.sync m16n8k16 fp16, ldmatrix(+trans), 3-stage cp.async, LSU de-bursted
// refill spread across ks slots, pipelined barrier at ks==3.
// MODE 0: g_h16[tile] = fp16(gelu(gather(g_xh) @ W1 + b1))
// MODE 1: g_y[orig]   = cw * (g_h16 @ W2 + b2)
// Ends with __syncthreads (stage buffers safe for the next tile).
// ---------------------------------------------------------------------------
#define MMA_F16(c, a0, a1, a2, a3, b0, b1)                                       \
    asm volatile("mma.sync.aligned.m16n8k16.row.col.f32.f16.f16.f32 "            \
        "{%0,%1,%2,%3}, {%4,%5,%6,%7}, {%8,%9}, {%0,%1,%2,%3};"                  \
        : "+f"((c)[0]), "+f"((c)[1]), "+f"((c)[2]), "+f"((c)[3])                  \
        : "r"(a0), "r"(a1), "r"(a2), "r"(a3), "r"(b0), "r"(b1))

template<int KDIM, int NDIM, int MODE>
__device__ __forceinline__ void do_tile(int mt, int nblk,
                                        const __half* __restrict__ X,
                                        const __half* __restrict__ W,
                                        const float* __restrict__ bias)
{
    int e = -1, m0 = 0, ne = 0, acc = 0;
    #pragma unroll
    for (int i = 0; i < E_; i++) {
        int n = g_cnt[i]; int nt = (n + BM - 1) / BM;
        if (e < 0 && mt < acc + nt) { e = i; m0 = (mt - acc) * BM; ne = n; }
        acc += nt;
    }
    if (e < 0) return;

    const int n0  = nblk * BN;
    const int tid = threadIdx.x;
    const int off = g_off[e];

    extern __shared__ char smem[];
    const uint32_t sbase = smem_u32(smem);

    // ---- A staging: rows (tid>>3)+32i, seg tid&7 ----
    const int a_seg = tid & 7;
    const int a_row0 = tid >> 3;
    const __half* aptr[4]; uint32_t abytes[4];
    #pragma unroll
    for (int i = 0; i < 4; i++) {
        int row = a_row0 + 32 * i;
        int m = m0 + row;
        bool v = (m < ne);
        int gi = off + (v ? m : 0);
        const __half* src = (MODE == 0) ? X + (size_t)g_tok[gi] * KDIM
                                        : g_h16 + (size_t)gi * KDIM;
        aptr[i]   = src + a_seg * 8;
        abytes[i] = v ? 16u : 0u;
    }
    const uint32_t a_s0 = (uint32_t)(a_row0 * ASTB + a_seg * 16);

    // ---- B staging: k-row (tid>>4)+16i, seg tid&15 ----
    const __half* bbase = W + (size_t)e * KDIM * NDIM + n0
                        + (size_t)(tid >> 4) * NDIM + (tid & 15) * 8;
    const uint32_t b_s0 = (uint32_t)((tid >> 4) * BSTB + (tid & 15) * 16);

    constexpr int KB = KDIM / BK;

    auto issue_a = [&](int stage, int kb) {
        uint32_t Ab = sbase + stage * STG;
        const int k0 = kb * BK;
        #pragma unroll
        for (int i = 0; i < 4; i++)
            cp16(Ab + a_s0 + (uint32_t)(i * 32 * ASTB), aptr[i] + k0, abytes[i]);
    };
    auto issue_b = [&](int stage, int kb) {
        uint32_t Bb = sbase + stage * STG + ASZ;
        const int k0 = kb * BK;
        #pragma unroll
        for (int i = 0; i < 4; i++)
            cp16(Bb + b_s0 + (uint32_t)(i * 16 * BSTB),
                 bbase + (size_t)(k0 + i * 16) * NDIM, 16u);
    };

    // ---- fragment geometry: 8 warps = 2m x 4n, each 64x32 ----
    const int lane = tid & 31, wid = tid >> 5;
    const int warp_m = (wid >> 2) * 64;
    const int warp_n = (wid & 3) * 32;
    const int fg = lane >> 2;
    const int ft = lane & 3;

    const uint32_t a_lm = (uint32_t)((warp_m + (lane & 15)) * ASTB + (lane >> 4) * 16);
    const uint32_t b_lm = (uint32_t)((lane & 15) * BSTB + (warp_n + (lane >> 4) * 8) * 2);

    float c[4][4][4];
    #pragma unroll
    for (int mf = 0; mf < 4; mf++)
        #pragma unroll
        for (int nf = 0; nf < 4; nf++)
            #pragma unroll
            for (int r = 0; r < 4; r++) c[mf][nf][r] = 0.f;

    #pragma unroll
    for (int s = 0; s < STAGES - 1; s++) { issue_a(s, s); issue_b(s, s); CP_COMMIT(); }
    CP_WAIT(STAGES - 2);        // chunk 0 landed
    __syncthreads();

    for (int kb = 0; kb < KB; kb++) {
        const int buf = kb % STAGES;
        const uint32_t Abuf = sbase + buf * STG + a_lm;
        const uint32_t Bbuf = sbase + buf * STG + ASZ + b_lm;
        const int nstage = (kb + STAGES - 1) % STAGES;
        const bool do_issue = (kb + STAGES - 1 < KB);

        #pragma unroll
        for (int ks = 0; ks < 4; ks++) {
            uint32_t a[4][4];
            #pragma unroll
            for (int mf = 0; mf < 4; mf++)
                LDMX4(a[mf][0], a[mf][1], a[mf][2], a[mf][3],
                      Abuf + (uint32_t)(mf * 16 * ASTB + ks * 32));
            uint32_t b[4][2];
            #pragma unroll
            for (int g = 0; g < 2; g++)
                LDMX4T(b[2 * g][0], b[2 * g][1], b[2 * g + 1][0], b[2 * g + 1][1],
                       Bbuf + (uint32_t)(ks * 16 * BSTB + g * 32));

            if (ks == 0 && do_issue) issue_a(nstage, kb + STAGES - 1);
            if (ks == 1 && do_issue) issue_b(nstage, kb + STAGES - 1);
            if (ks == 2) CP_COMMIT();
            if (ks == 3 && kb + 1 < KB) {
                CP_WAIT(STAGES - 2);
                __syncthreads();
            }

            #pragma unroll
            for (int mf = 0; mf < 4; mf++)
                #pragma unroll
                for (int nf = 0; nf < 4; nf++)
                    MMA_F16(c[mf][nf], a[mf][0], a[mf][1], a[mf][2], a[mf][3],
                            b[nf][0], b[nf][1]);
        }
    }

    // ---- epilogue ----
    const float* bb = bias + (size_t)e * NDIM + n0;
    #pragma unroll
    for (int mf = 0; mf < 4; mf++) {
        #pragma unroll
        for (int half = 0; half < 2; half++) {
            int r = warp_m + mf * 16 + fg + half * 8;
            int m = m0 + r;
            if (m >= ne) continue;
            int gi = off + m;
            if (MODE == 0) {
                __half* drow = g_h16 + (size_t)gi * F_ + n0;
                #pragma unroll
                for (int nf = 0; nf < 4; nf++) {
                    int col = warp_n + nf * 8 + 2 * ft;
                    float2 bv = *(const float2*)(bb + col);
                    float v0 = gelu_exact(c[mf][nf][half * 2 + 0] + bv.x);
                    float v1 = gelu_exact(c[mf][nf][half * 2 + 1] + bv.y);
                    __half2 hv = __floats2half2_rn(v0, v1);
                    *(uint32_t*)(drow + col) = *(uint32_t*)&hv;
                }
            } else {
                float cw = g_cw[gi];
                float* drow = g_y + (size_t)g_orig[gi] * H_ + n0;
                #pragma unroll
                for (int nf = 0; nf < 4; nf++) {
                    int col = warp_n + nf * 8 + 2 * ft;
                    float2 bv = *(const float2*)(bb + col);
                    float2 o;
                    o.x = cw * (c[mf][nf][half * 2 + 0] + bv.x);
                    o.y = cw * (c[mf][nf][half * 2 + 1] + bv.y);
                    *(float2*)(drow + col) = o;
                }
            }
        }
    }
}

// ---------------------------------------------------------------------------
// Persistent fused GEMM: phase 1 drains GEMM1 tiles via a global work queue
// (mt-major), flagging per-mt completion; phase 2 drains GEMM2 tiles, each
// spin-waiting its mt's 32 producer tiles. Deadlock-free: a CTA enters phase 2
// only after the phase-1 queue is exhausted, so awaited tiles are resident.
// ---------------------------------------------------------------------------
__global__ void __launch_bounds__(NTH, 2)
k_fused(const __half* __restrict__ xh, const __half* __restrict__ w1h,
        const __half* __restrict__ w2h,
        const float* __restrict__ b1, const float* __restrict__ b2)
{
    __shared__ int s_tile;

    // ---- Phase 1: GEMM1 ----
    for (;;) {
        if (threadIdx.x == 0) s_tile = atomicAdd(&g_t1, 1);
        __syncthreads();
        int t = s_tile;
        __syncthreads();               // s_tile stable before next overwrite
        if (t >= N1_) break;
        int mt = t >> 5, nblk = t & 31;
        do_tile<H_, F_, 0>(mt, nblk, xh, w1h, b1);
        __syncthreads();               // stage buffers free for next tile
        if (threadIdx.x == 0) {
            __threadfence();           // h16 visible device-wide before flag
            atomicAdd(&g_done[mt], 1);
        }
    }

    // ---- Phase 2: GEMM2 ----
    for (;;) {
        if (threadIdx.x == 0) s_tile = atomicAdd(&g_t2, 1);
        __syncthreads();
        int t = s_tile;
        __syncthreads();
        if (t >= N2_) break;
        int mt = t >> 3, nblk = t & 7;
        if (threadIdx.x == 0) {
            while (*(volatile int*)&g_done[mt] != 32) { }
            __threadfence();
        }
        __syncthreads();               // all threads ordered after flag
        do_tile<F_, H_, 1>(mt, nblk, nullptr, w2h, b2);
        __syncthreads();
    }
}

// ---------------------------------------------------------------------------
// Final reduce over the K=2 slots of each token
// ---------------------------------------------------------------------------
__global__ void k_reduce(const void* sel, float* __restrict__ out) {
    int i4 = blockIdx.x * blockDim.x + threadIdx.x;
    if (i4 >= T_ * H_ / 4) return;
    int t = i4 / (H_ / 4);
    int c = i4 % (H_ / 4);
    float4 s = make_float4(0.f, 0.f, 0.f, 0.f);
    if (g_allvalid) {
        float4 v0 = ((const float4*)g_y)[(size_t)(t * KTOP_ + 0) * (H_ / 4) + c];
        float4 v1 = ((const float4*)g_y)[(size_t)(t * KTOP_ + 1) * (H_ / 4) + c];
        s.x = v0.x + v1.x; s.y = v0.y + v1.y; s.z = v0.z + v1.z; s.w = v0.w + v1.w;
    } else {
        #pragma unroll
        for (int k = 0; k < KTOP_; k++) {
            int e = sel_get(sel, t * KTOP_ + k);
            if (e >= 0 && e < E_) {
                float4 v = ((const float4*)g_y)[(size_t)(t * KTOP_ + k) * (H_ / 4) + c];
                s.x += v.x; s.y += v.y; s.z += v.z; s.w += v.w;
            }
        }
    }
    ((float4*)out)[i4] = s;
}

// ---------------------------------------------------------------------------
// Launch
// ---------------------------------------------------------------------------
extern "C" void kernel_launch(void* const* d_in, const int* in_sizes, int n_in,
                              void* d_out, int out_size) {
    const float* hidden = (const float*)d_in[0];
    const float* ew     = (const float*)d_in[1];
    const float* W1     = (const float*)d_in[2];
    const float* b1     = (const float*)d_in[3];
    const float* W2     = (const float*)d_in[4];
    const float* b2     = (const float*)d_in[5];
    const void*  sel    = d_in[6];
    float* out = (float*)d_out;

    cudaFuncSetAttribute(k_fused, cudaFuncAttributeMaxDynamicSharedMemorySize, SMEM_TOTAL);

    __half* xh;  cudaGetSymbolAddress((void**)&xh,  g_xh);
    __half* w1h; cudaGetSymbolAddress((void**)&w1h, g_w1h);
    __half* w2h; cudaGetSymbolAddress((void**)&w2h, g_w2h);

    k_route<<<1, 1024>>>(sel, ew);
    k_half3<<<4096, 256>>>((const float4*)hidden, (const float4*)W1, (const float4*)W2);

    k_fused<<<296, NTH, SMEM_TOTAL>>>(xh, w1h, w2h, b1, b2);

    k_reduce<<<(T_ * H_ / 4 + 255) / 256, 256>>>(sel, out);
}